// round 9
// baseline (speedup 1.0000x reference)
#include <cuda_runtime.h>
#include <cuda_bf16.h>

#define RDIM 256
#define SDIM 256
#define CH   32                 // rows staged per chunk
#define NCHUNK (RDIM / CH)      // 8
#define PSTRIDE 260             // smem row stride in floats (256 + 4 pad, 16B-aligned)
#define NEG_INF (-1e30f)

__device__ __forceinline__ void consider(
    float v, int s, float &a0, int &x0, float &a1, int &x1, float &a2, int &x2)
{
    if (v > a2) {
        if (v > a0)      { a2 = a1; x2 = x1; a1 = a0; x1 = x0; a0 = v; x0 = s; }
        else if (v > a1) { a2 = a1; x2 = x1; a1 = v;  x1 = s; }
        else             { a2 = v;  x2 = s; }
    }
}

__global__ __launch_bounds__(512)
void ipm_kernel(const float* __restrict__ msm,
                const int* __restrict__ refm,     // bool promoted to int32
                const int* __restrict__ srcm,     // bool promoted to int32
                float* __restrict__ out_score,
                float* __restrict__ out_corr)     // bool output stored as float32
{
    __shared__ float stile[CH * PSTRIDE];         // 33,280 B

    const int p   = blockIdx.x;
    const int tid = threadIdx.x;                  // 0..511

    const float* __restrict__ tile = msm + (size_t)p * RDIM * SDIM;
    float* __restrict__ oscore = out_score + (size_t)p * RDIM * SDIM;
    float* __restrict__ ocorr  = out_corr  + (size_t)p * RDIM * SDIM;

    // Running top-3 of RAW scores (exp is monotonic; applied to winners only).
    // tid<256: column t = tid.   tid>=256: row u = tid-256 (active in one chunk).
    float b0 = NEG_INF, b1 = NEG_INF, b2 = NEG_INF;
    int   j0 = 0,       j1 = 0,       j2 = 0;

    const float4 z4 = make_float4(0.f, 0.f, 0.f, 0.f);

    for (int c = 0; c < NCHUNK; ++c) {
        if (c > 0) __syncthreads();               // prev chunk consumers done

        // ---- stage 32 rows into smem: 2048 float4, 4 per thread, coalesced --
        const float4* __restrict__ gsrc =
            (const float4*)(tile + (size_t)(c * CH) * SDIM);
        #pragma unroll
        for (int k = 0; k < 4; ++k) {
            int idx = tid + 512 * k;              // 0..2047
            int rl  = idx >> 6;                   // row-local (64 float4 per row)
            int s4  = idx & 63;
            float4 q = gsrc[idx];
            *(float4*)&stile[rl * PSTRIDE + 4 * s4] = q;
        }
        __syncthreads();

        if (tid < 256) {
            // column t: partial scan over this chunk's 32 rows (bank-conflict-free)
            const int t = tid;
            #pragma unroll 8
            for (int rl = 0; rl < CH; ++rl) {
                consider(stile[rl * PSTRIDE + t], c * CH + rl,
                         b0, j0, b1, j1, b2, j2);
            }
        } else {
            const int u = tid - 256;              // global row index
            if ((u >> 5) == c) {
                // this thread's row is resident: contiguous LDS.128 scan
                const int rl = u & (CH - 1);
                const float4* __restrict__ srow = (const float4*)&stile[rl * PSTRIDE];
                #pragma unroll 8
                for (int k4 = 0; k4 < SDIM / 4; ++k4) {
                    float4 q = srow[k4];
                    int s = 4 * k4;
                    consider(q.x, s + 0, b0, j0, b1, j1, b2, j2);
                    consider(q.y, s + 1, b0, j0, b1, j1, b2, j2);
                    consider(q.z, s + 2, b0, j0, b1, j1, b2, j2);
                    consider(q.w, s + 3, b0, j0, b1, j1, b2, j2);
                }
            }
        }

        // ---- zero-fill 1/8 of both output maps (overlaps next chunk's loads)
        {
            float4* zs = (float4*)oscore + c * 2048;
            float4* zc = (float4*)ocorr  + c * 2048;
            #pragma unroll
            for (int i = tid; i < 2048; i += 512) {
                zs[i] = z4;
                zc[i] = z4;
            }
        }
    }
    __syncthreads();   // all zero-fill + all scans complete before scatter

    // ---------------- scatter (exp applied to the 3 winners only) ------------
    float vs[3] = {__expf(b0), __expf(b1), __expf(b2)};
    int   is[3] = {j0, j1, j2};

    if (tid < 256) {
        // Column t's top-3 along R
        const int t = tid;
        const bool ms = srcm[(size_t)p * SDIM + t] != 0;
        #pragma unroll
        for (int k = 0; k < 3; ++k) {
            int r = is[k];
            float v = vs[k];
            atomicAdd(&oscore[r * SDIM + t], 0.5f * v);
            if (v > 0.0f && ms && refm[(size_t)p * RDIM + r] != 0)
                ocorr[r * SDIM + t] = 1.0f;   // idempotent write, benign race
        }
    } else {
        // Row u's top-3 along S
        const int t = tid - 256;
        const bool mr = refm[(size_t)p * RDIM + t] != 0;
        #pragma unroll
        for (int k = 0; k < 3; ++k) {
            int s = is[k];
            float v = vs[k];
            atomicAdd(&oscore[t * SDIM + s], 0.5f * v);
            if (v > 0.0f && mr && srcm[(size_t)p * SDIM + s] != 0)
                ocorr[t * SDIM + s] = 1.0f;
        }
    }
}

extern "C" void kernel_launch(void* const* d_in, const int* in_sizes, int n_in,
                              void* d_out, int out_size)
{
    // metadata order: matching_score_map [P,R,S] f32, node_corr_scores [P] f32 (unused),
    //                 ref_knn_masks [P,R] bool->int32, src_knn_masks [P,S] bool->int32
    const float* msm  = (const float*)d_in[0];
    const int*   refm = (const int*)d_in[2];
    const int*   srcm = (const int*)d_in[3];

    const int P = in_sizes[1];                 // node_corr_scores has P elements
    float* out_score = (float*)d_out;
    float* out_corr  = out_score + (size_t)P * RDIM * SDIM;  // bool output as float32

    ipm_kernel<<<P, 512>>>(msm, refm, srcm, out_score, out_corr);
}

// round 10
// speedup vs baseline: 1.4728x; 1.4728x over previous
#include <cuda_runtime.h>
#include <cuda_bf16.h>

#define RDIM 256
#define SDIM 256
#define NEG_INF (-1e30f)

// Stable comparator: value descending, index ascending on ties (matches jax top_k).
__device__ __forceinline__ bool better(float a, int i, float b, int j)
{
    return (a > b) || (a == b && i < j);
}

// Merge two triples, each sorted by `better`, into the top-3 (in a).
__device__ __forceinline__ void merge3(
    float &a0, int &i0, float &a1, int &i1, float &a2, int &i2,
    float b0, int j0, float b1, int j1, float b2, int j2)
{
    float o0, o1, o2; int p0, p1, p2;
    if (better(a0, i0, b0, j0)) { o0 = a0; p0 = i0; a0 = a1; i0 = i1; a1 = a2; i1 = i2; }
    else                        { o0 = b0; p0 = j0; b0 = b1; j0 = j1; b1 = b2; j1 = j2; }
    if (better(a0, i0, b0, j0)) { o1 = a0; p1 = i0; a0 = a1; i0 = i1; }
    else                        { o1 = b0; p1 = j0; b0 = b1; j0 = j1; }
    if (better(a0, i0, b0, j0)) { o2 = a0; p2 = i0; }
    else                        { o2 = b0; p2 = j0; }
    a0 = o0; i0 = p0; a1 = o1; i1 = p1; a2 = o2; i2 = p2;
}

// Sequential stable top-3 update (strict >, ascending index scan order).
__device__ __forceinline__ void consider(
    float v, int s, float &a0, int &x0, float &a1, int &x1, float &a2, int &x2)
{
    if (v > a2) {
        if (v > a0)      { a2 = a1; x2 = x1; a1 = a0; x1 = x0; a0 = v; x0 = s; }
        else if (v > a1) { a2 = a1; x2 = x1; a1 = v;  x1 = s; }
        else             { a2 = v;  x2 = s; }
    }
}

__global__ __launch_bounds__(512)
void ipm_kernel(const float* __restrict__ msm,
                const int* __restrict__ refm,     // bool promoted to int32
                const int* __restrict__ srcm,     // bool promoted to int32
                float* __restrict__ out_score,
                float* __restrict__ out_corr)     // bool output stored as float32
{
    const int p = blockIdx.x;
    const int tid = threadIdx.x;                  // 0..511

    const float* __restrict__ tile = msm + (size_t)p * RDIM * SDIM;
    float* __restrict__ oscore = out_score + (size_t)p * RDIM * SDIM;
    float* __restrict__ ocorr  = out_corr  + (size_t)p * RDIM * SDIM;

    __shared__ float s_rval[RDIM][3];   // per-row top-3 values (raw scores)
    __shared__ int   s_ridx[RDIM][3];   // per-row top-3 src indices

    // Column-half registers (top-3 of raw scores; exp applied at scatter)
    float b0 = NEG_INF, b1 = NEG_INF, b2 = NEG_INF;
    int   j0 = 0,       j1 = 0,       j2 = 0;

    if (tid < 256) {
        // ---- column top-3 for column t = tid (scan r; coalesced across lanes)
        const int t = tid;
        #pragma unroll 8
        for (int r = 0; r < RDIM; ++r) {
            float v = tile[r * SDIM + t];
            consider(v, r, b0, j0, b1, j1, b2, j2);
        }
    } else {
        // ---- warp-cooperative row top-3: 8 warps x 32 rows, 512B-contiguous loads
        const int w    = (tid - 256) >> 5;   // 0..7
        const int lane = tid & 31;
        #pragma unroll 2
        for (int i = 0; i < 32; ++i) {
            const int r = w + 8 * i;                        // interleaved sweep
            const float4* __restrict__ row = (const float4*)(tile + (size_t)r * SDIM);
            float4 qa = row[lane];                          // cols [4*lane, 4*lane+4)
            float4 qb = row[lane + 32];                     // cols [128+4*lane, ...)

            float a0 = NEG_INF, a1 = NEG_INF, a2 = NEG_INF;
            int   x0 = 0,       x1 = 0,       x2 = 0;
            consider(qa.x, 4*lane + 0,   a0,x0,a1,x1,a2,x2);
            consider(qa.y, 4*lane + 1,   a0,x0,a1,x1,a2,x2);
            consider(qa.z, 4*lane + 2,   a0,x0,a1,x1,a2,x2);
            consider(qa.w, 4*lane + 3,   a0,x0,a1,x1,a2,x2);
            consider(qb.x, 128+4*lane+0, a0,x0,a1,x1,a2,x2);
            consider(qb.y, 128+4*lane+1, a0,x0,a1,x1,a2,x2);
            consider(qb.z, 128+4*lane+2, a0,x0,a1,x1,a2,x2);
            consider(qb.w, 128+4*lane+3, a0,x0,a1,x1,a2,x2);

            // butterfly merge with stable comparator -> identical top-3 in all lanes
            #pragma unroll
            for (int off = 16; off >= 1; off >>= 1) {
                float c0 = __shfl_xor_sync(0xffffffffu, a0, off);
                float c1 = __shfl_xor_sync(0xffffffffu, a1, off);
                float c2 = __shfl_xor_sync(0xffffffffu, a2, off);
                int   y0 = __shfl_xor_sync(0xffffffffu, x0, off);
                int   y1 = __shfl_xor_sync(0xffffffffu, x1, off);
                int   y2 = __shfl_xor_sync(0xffffffffu, x2, off);
                merge3(a0, x0, a1, x1, a2, x2, c0, y0, c1, y1, c2, y2);
            }
            if (lane < 3) {
                float v = (lane == 0) ? a0 : (lane == 1) ? a1 : a2;
                int   s = (lane == 0) ? x0 : (lane == 1) ? x1 : x2;
                s_rval[r][lane] = v;
                s_ridx[r][lane] = s;
            }
        }
    }

    // ---------------- zero-fill both output tiles (512 threads, float4) ------
    {
        float4 z4 = make_float4(0.f, 0.f, 0.f, 0.f);
        float4* zs = (float4*)oscore;
        float4* zc = (float4*)ocorr;
        #pragma unroll 8
        for (int i = tid; i < (RDIM * SDIM) / 4; i += 512) {
            zs[i] = z4;
            zc[i] = z4;
        }
    }
    __syncthreads();   // zero-fill + row results visible before scatter

    // ---------------- scatter (exp applied to winners only) ------------------
    if (tid < 256) {
        // Column t's top-3 along R
        const int t = tid;
        const bool ms = srcm[(size_t)p * SDIM + t] != 0;
        float vs[3] = {__expf(b0), __expf(b1), __expf(b2)};
        int   is[3] = {j0, j1, j2};
        #pragma unroll
        for (int k = 0; k < 3; ++k) {
            int r = is[k];
            float v = vs[k];
            atomicAdd(&oscore[r * SDIM + t], 0.5f * v);
            if (v > 0.0f && ms && refm[(size_t)p * RDIM + r] != 0)
                ocorr[r * SDIM + t] = 1.0f;   // idempotent write, benign race
        }
    } else {
        // Row t's top-3 along S (from smem)
        const int t = tid - 256;
        const bool mr = refm[(size_t)p * RDIM + t] != 0;
        #pragma unroll
        for (int k = 0; k < 3; ++k) {
            int s = s_ridx[t][k];
            float v = __expf(s_rval[t][k]);
            atomicAdd(&oscore[t * SDIM + s], 0.5f * v);
            if (v > 0.0f && mr && srcm[(size_t)p * SDIM + s] != 0)
                ocorr[t * SDIM + s] = 1.0f;
        }
    }
}

extern "C" void kernel_launch(void* const* d_in, const int* in_sizes, int n_in,
                              void* d_out, int out_size)
{
    // metadata order: matching_score_map [P,R,S] f32, node_corr_scores [P] f32 (unused),
    //                 ref_knn_masks [P,R] bool->int32, src_knn_masks [P,S] bool->int32
    const float* msm  = (const float*)d_in[0];
    const int*   refm = (const int*)d_in[2];
    const int*   srcm = (const int*)d_in[3];

    const int P = in_sizes[1];                 // node_corr_scores has P elements
    float* out_score = (float*)d_out;
    float* out_corr  = out_score + (size_t)P * RDIM * SDIM;  // bool output as float32

    ipm_kernel<<<P, 512>>>(msm, refm, srcm, out_score, out_corr);
}

// round 11
// speedup vs baseline: 1.7085x; 1.1601x over previous
#include <cuda_runtime.h>
#include <cuda_bf16.h>

#define RDIM 256
#define SDIM 256
#define NEG_INF (-1e30f)

__device__ __forceinline__ void consider(
    float v, int s, float &a0, int &x0, float &a1, int &x1, float &a2, int &x2)
{
    if (v > a2) {                          // rare after warm-up (~17/256 taken)
        if (v > a0)      { a2 = a1; x2 = x1; a1 = a0; x1 = x0; a0 = v; x0 = s; }
        else if (v > a1) { a2 = a1; x2 = x1; a1 = v;  x1 = s; }
        else             { a2 = v;  x2 = s; }
    }
}

__global__ __launch_bounds__(512)
void ipm_kernel(const float* __restrict__ msm,
                const int* __restrict__ refm,     // bool promoted to int32
                const int* __restrict__ srcm,     // bool promoted to int32
                float* __restrict__ out_score,
                float* __restrict__ out_corr)     // bool output stored as float32
{
    const int p = blockIdx.x;
    const int tid = threadIdx.x;                  // 0..511

    const float* __restrict__ tile = msm + (size_t)p * RDIM * SDIM;
    float* __restrict__ oscore = out_score + (size_t)p * RDIM * SDIM;
    float* __restrict__ ocorr  = out_corr  + (size_t)p * RDIM * SDIM;

    // ---------------- zero-fill FIRST (independent stores drain under scans) --
    // __stcs: streaming/evict-first so the 268MB write stream doesn't evict
    // the tile lines needed by the second (row) read pass.
    {
        const float4 z4 = make_float4(0.f, 0.f, 0.f, 0.f);
        float4* zs = (float4*)oscore;
        float4* zc = (float4*)ocorr;
        #pragma unroll 8
        for (int i = tid; i < (RDIM * SDIM) / 4; i += 512) {
            __stcs(&zs[i], z4);
            __stcs(&zc[i], z4);
        }
    }

    // top-3 of RAW scores (exp is monotonic; exp applied to winners only)
    float b0 = NEG_INF, b1 = NEG_INF, b2 = NEG_INF;
    int   j0 = 0,       j1 = 0,       j2 = 0;

    if (tid < 256) {
        // ---- column top-3 for column t = tid (scan r; coalesced across lanes)
        const int t = tid;
        #pragma unroll 8
        for (int r = 0; r < RDIM; ++r) {
            float v = tile[r * SDIM + t];
            consider(v, r, b0, j0, b1, j1, b2, j2);
        }
    } else {
        // ---- row top-3 for row t = tid-256 (contiguous float4 per thread)
        const int t = tid - 256;
        const float4* __restrict__ row = (const float4*)(tile + (size_t)t * SDIM);
        #pragma unroll 8
        for (int j = 0; j < SDIM / 4; ++j) {
            float4 q = row[j];
            int s = 4 * j;
            consider(q.x, s + 0, b0, j0, b1, j1, b2, j2);
            consider(q.y, s + 1, b0, j0, b1, j1, b2, j2);
            consider(q.z, s + 2, b0, j0, b1, j1, b2, j2);
            consider(q.w, s + 3, b0, j0, b1, j1, b2, j2);
        }
    }

    __syncthreads();   // zero-fill by whole block visible before scatter

    // ---------------- scatter (exp applied to the 3 winners only) ------------
    float vs[3] = {__expf(b0), __expf(b1), __expf(b2)};
    int   is[3] = {j0, j1, j2};

    if (tid < 256) {
        // Column t's top-3 along R
        const int t = tid;
        const bool ms = srcm[(size_t)p * SDIM + t] != 0;
        #pragma unroll
        for (int k = 0; k < 3; ++k) {
            int r = is[k];
            float v = vs[k];
            atomicAdd(&oscore[r * SDIM + t], 0.5f * v);
            if (v > 0.0f && ms && refm[(size_t)p * RDIM + r] != 0)
                ocorr[r * SDIM + t] = 1.0f;   // idempotent write, benign race
        }
    } else {
        // Row t's top-3 along S
        const int t = tid - 256;
        const bool mr = refm[(size_t)p * RDIM + t] != 0;
        #pragma unroll
        for (int k = 0; k < 3; ++k) {
            int s = is[k];
            float v = vs[k];
            atomicAdd(&oscore[t * SDIM + s], 0.5f * v);
            if (v > 0.0f && mr && srcm[(size_t)p * SDIM + s] != 0)
                ocorr[t * SDIM + s] = 1.0f;
        }
    }
}

extern "C" void kernel_launch(void* const* d_in, const int* in_sizes, int n_in,
                              void* d_out, int out_size)
{
    // metadata order: matching_score_map [P,R,S] f32, node_corr_scores [P] f32 (unused),
    //                 ref_knn_masks [P,R] bool->int32, src_knn_masks [P,S] bool->int32
    const float* msm  = (const float*)d_in[0];
    const int*   refm = (const int*)d_in[2];
    const int*   srcm = (const int*)d_in[3];

    const int P = in_sizes[1];                 // node_corr_scores has P elements
    float* out_score = (float*)d_out;
    float* out_corr  = out_score + (size_t)P * RDIM * SDIM;  // bool output as float32

    ipm_kernel<<<P, 512>>>(msm, refm, srcm, out_score, out_corr);
}